// round 5
// baseline (speedup 1.0000x reference)
#include <cuda_runtime.h>
#include <cuda_bf16.h>
#include <cub/cub.cuh>
#include <math.h>

#define FHh 100
#define FWw 160
#define NPIX 16000
#define CIN 512
#define NANCH 144000
#define PRE 6000
#define POST 300
#define SCORES_OFF 0
#define REG_OFF 144000
#define PROP_OFF 720000
#define CUB_TEMP_CAP (1 << 24)

// ---------------- static device scratch (no allocations allowed) ----------------
__device__ __align__(256) float g_y[NPIX * CIN];        // relu(conv1) output, NHWC
__device__ __align__(256) float g_wf[CIN * 64];          // fused 1x1 weights [ic][64]
__device__ float g_bf[64];                               // fused bias
__device__ __align__(256) float g_zero[CIN];             // stays zero: SAME-padding source
__device__ __align__(256) unsigned g_keys_in[NANCH];
__device__ __align__(256) unsigned g_vals_in[NANCH];
__device__ __align__(256) unsigned g_keys_out[NANCH];
__device__ __align__(256) unsigned g_vals_out[NANCH];
__device__ __align__(256) unsigned char g_cub_temp[CUB_TEMP_CAP];
__device__ __align__(256) float4 g_boxes[PRE];
__device__ int g_valid[PRE];

// ---------------- pack fused 1x1 weights ----------------
__global__ void pack_kernel(const float* __restrict__ Wc, const float* __restrict__ bc,
                            const float* __restrict__ Wr, const float* __restrict__ br) {
    int i = blockIdx.x * blockDim.x + threadIdx.x;
    if (i < CIN * 64) {
        int ic = i >> 6, o = i & 63;
        float v = 0.f;
        if (o < 9)       v = Wc[ic * 9 + o];
        else if (o < 45) v = Wr[ic * 36 + (o - 9)];
        g_wf[i] = v;
    }
    if (i < 64) {
        float v = 0.f;
        if (i < 9)       v = bc[i];
        else if (i < 45) v = br[i - 9];
        g_bf[i] = v;
    }
}

// ---------------- 3x3 conv 512->512 + bias + relu (fp32, R1-identical numerics) ----------------
// block: 64 pixels x 256 oc. 256 threads, each computes 4 px x 16 oc.
// Accumulation per output: strict sequential (tap, ic) FFMA chain == R1 (passed).
__global__ __launch_bounds__(256, 2)
void conv3x3_kernel(const float* __restrict__ F, const float* __restrict__ W1,
                    const float* __restrict__ b1) {
    __shared__ float4 Ws[16 * 64];  // [ic=16][oc=256] as float4

    const int tid = threadIdx.x;
    const int pg = tid >> 4;          // 0..15 pixel group
    const int ocg = tid & 15;         // 0..15 oc group (16 oc each)
    const int pbase = blockIdx.x * 64 + pg * 4;
    const int ocblk = blockIdx.y * 256;
    const int oc = ocblk + ocg * 16;

    float acc[4][16];
#pragma unroll
    for (int k = 0; k < 4; k++)
#pragma unroll
        for (int j = 0; j < 16; j++) acc[k][j] = 0.f;

    int py[4], px[4];
#pragma unroll
    for (int k = 0; k < 4; k++) {
        int p = pbase + k;
        py[k] = p / FWw;
        px[k] = p % FWw;
    }

    // weight staging address for this thread (4 consecutive float4 = 64B)
    const int wr = tid >> 4;            // row 0..15 (ic within chunk)
    const int wc4 = (tid & 15) * 4;     // float4 col 0..60

    for (int tap = 0; tap < 9; tap++) {
        const int dy = tap / 3 - 1;
        const int dx = tap % 3 - 1;
        const float* aptr[4];
#pragma unroll
        for (int k = 0; k < 4; k++) {
            int yy = py[k] + dy, xx = px[k] + dx;
            bool v = (yy >= 0) && (yy < FHh) && (xx >= 0) && (xx < FWw);
            aptr[k] = v ? (F + (size_t)(yy * FWw + xx) * CIN) : g_zero;
        }
        const float* wtap = W1 + (size_t)tap * CIN * CIN + ocblk;

        for (int icc = 0; icc < CIN / 16; icc++) {
            const float* src = wtap + (size_t)(icc * 16 + wr) * CIN + wc4 * 4;
#pragma unroll
            for (int q = 0; q < 4; q++)
                Ws[wr * 64 + wc4 + q] = *(const float4*)(src + q * 4);
            __syncthreads();
#pragma unroll
            for (int i = 0; i < 16; i++) {
                const int ic = icc * 16 + i;
                float av[4];
                av[0] = aptr[0][ic];
                av[1] = aptr[1][ic];
                av[2] = aptr[2][ic];
                av[3] = aptr[3][ic];
                float4 w0 = Ws[i * 64 + ocg * 4];
                float4 w1 = Ws[i * 64 + ocg * 4 + 1];
                float4 w2 = Ws[i * 64 + ocg * 4 + 2];
                float4 w3 = Ws[i * 64 + ocg * 4 + 3];
                float wv[16] = {w0.x, w0.y, w0.z, w0.w, w1.x, w1.y, w1.z, w1.w,
                                w2.x, w2.y, w2.z, w2.w, w3.x, w3.y, w3.z, w3.w};
#pragma unroll
                for (int k = 0; k < 4; k++)
#pragma unroll
                    for (int j = 0; j < 16; j++) acc[k][j] += av[k] * wv[j];
            }
            __syncthreads();
        }
    }

    // epilogue: +bias, relu, store (same as R1)
    float bb[16];
#pragma unroll
    for (int q = 0; q < 4; q++) {
        float4 bv = *(const float4*)(b1 + oc + q * 4);
        bb[q * 4 + 0] = bv.x; bb[q * 4 + 1] = bv.y;
        bb[q * 4 + 2] = bv.z; bb[q * 4 + 3] = bv.w;
    }
#pragma unroll
    for (int k = 0; k < 4; k++) {
        int p = pbase + k;
#pragma unroll
        for (int q = 0; q < 4; q++) {
            float4 o;
            o.x = fmaxf(acc[k][q * 4 + 0] + bb[q * 4 + 0], 0.f);
            o.y = fmaxf(acc[k][q * 4 + 1] + bb[q * 4 + 1], 0.f);
            o.z = fmaxf(acc[k][q * 4 + 2] + bb[q * 4 + 2], 0.f);
            o.w = fmaxf(acc[k][q * 4 + 3] + bb[q * 4 + 3], 0.f);
            *(float4*)&g_y[(size_t)p * CIN + oc + q * 4] = o;
        }
    }
}

// ---------------- fused 1x1 heads: scores (sigmoid) + reg, emit sort keys ----------------
__global__ __launch_bounds__(256)
void head_kernel(float* __restrict__ out) {
    const int tid = threadIdx.x;
    const int pxi = blockIdx.x * 32 + (tid >> 3);
    const int grp = tid & 7;

    float acc[8];
#pragma unroll
    for (int j = 0; j < 8; j++) acc[j] = g_bf[grp * 8 + j];

    const float* yrow = g_y + (size_t)pxi * CIN;
    const float4* wf4 = (const float4*)g_wf;
#pragma unroll 4
    for (int ic = 0; ic < CIN; ic++) {
        float a = __ldg(yrow + ic);
        float4 w0 = __ldg(wf4 + ic * 16 + grp * 2);
        float4 w1 = __ldg(wf4 + ic * 16 + grp * 2 + 1);
        acc[0] += a * w0.x; acc[1] += a * w0.y; acc[2] += a * w0.z; acc[3] += a * w0.w;
        acc[4] += a * w1.x; acc[5] += a * w1.y; acc[6] += a * w1.z; acc[7] += a * w1.w;
    }

#pragma unroll
    for (int j = 0; j < 8; j++) {
        int o = grp * 8 + j;
        if (o < 9) {
            float s = 1.f / (1.f + expf(-acc[j]));
            int idx = pxi * 9 + o;
            out[SCORES_OFF + idx] = s;
            g_keys_in[idx] = __float_as_uint(s);  // positive floats: uint order == float order
            g_vals_in[idx] = (unsigned)idx;
        } else if (o < 45) {
            out[REG_OFF + pxi * 36 + (o - 9)] = acc[j];
        }
    }
}

// ---------------- decode + clip + min-size for the top-6000 ----------------
__global__ void decode_kernel(const float* __restrict__ AM, const float* __restrict__ out) {
    int r = blockIdx.x * blockDim.x + threadIdx.x;
    if (r >= PRE) return;
    int idx = (int)g_vals_out[r];
    float4 an = __ldg((const float4*)AM + idx);
    float4 dl = *(const float4*)(out + REG_OFF + (size_t)idx * 4);
    float ah = an.z - an.x, aw = an.w - an.y;
    float acy = an.x + 0.5f * ah, acx = an.y + 0.5f * aw;
    float cy = acy + dl.x * ah, cx = acx + dl.y * aw;
    float h = ah * expf(dl.z), w = aw * expf(dl.w);
    float y1 = fmaxf(cy - 0.5f * h, 0.f);
    float x1 = fmaxf(cx - 0.5f * w, 0.f);
    float y2 = fminf(cy + 0.5f * h, 1600.f);
    float x2 = fminf(cx + 0.5f * w, 2560.f);
    g_boxes[r] = make_float4(y1, x1, y2, x2);
    g_valid[r] = (((y2 - y1) >= 16.f) && ((x2 - x1) >= 16.f)) ? 1 : 0;
}

// ---------------- greedy NMS (== reference argmax/suppress scan), single block ----------------
__global__ __launch_bounds__(1024)
void nms_kernel(float* __restrict__ outp) {
    __shared__ unsigned char alive[PRE];
    __shared__ int s_found;
    __shared__ int s_ptr;
    __shared__ float4 s_box;

    const int tid = threadIdx.x;
    for (int i = tid; i < PRE; i += 1024) alive[i] = (unsigned char)g_valid[i];
    if (tid == 0) s_ptr = 0;
    __syncthreads();

    for (int slot = 0; slot < POST; slot++) {
        if (tid < 32) {
            int p = s_ptr;
            int found = -1;
            while (p < PRE) {
                int i = p + tid;
                bool a = (i < PRE) && alive[i];
                unsigned m = __ballot_sync(0xffffffffu, a);
                if (m) { found = p + __ffs(m) - 1; break; }
                p += 32;
            }
            if (tid == 0) {
                s_found = found;
                if (found >= 0) {
                    alive[found] = 0;
                    s_ptr = found + 1;
                    s_box = g_boxes[found];
                } else {
                    s_ptr = PRE;
                }
            }
        }
        __syncthreads();
        int f = s_found;
        if (f < 0) {
            for (int i = slot * 4 + tid; i < POST * 4; i += 1024) outp[i] = 0.f;
            return;
        }
        float4 b = s_box;
        if (tid == 0) {
            outp[slot * 4 + 0] = b.x;
            outp[slot * 4 + 1] = b.y;
            outp[slot * 4 + 2] = b.z;
            outp[slot * 4 + 3] = b.w;
        }
        float ba = fmaxf(b.z - b.x, 0.f) * fmaxf(b.w - b.y, 0.f);
        for (int i = f + 1 + tid; i < PRE; i += 1024) {
            if (alive[i]) {
                float4 c = __ldg((const float4*)g_boxes + i);
                float yy1 = fmaxf(b.x, c.x), xx1 = fmaxf(b.y, c.y);
                float yy2 = fminf(b.z, c.z), xx2 = fminf(b.w, c.w);
                float inter = fmaxf(yy2 - yy1, 0.f) * fmaxf(xx2 - xx1, 0.f);
                float ca = fmaxf(c.z - c.x, 0.f) * fmaxf(c.w - c.y, 0.f);
                float iou = inter / (ba + ca - inter + 1e-8f);
                if (iou > 0.7f) alive[i] = 0;
            }
        }
        __syncthreads();
    }
}

// ---------------- host launcher ----------------
extern "C" void kernel_launch(void* const* d_in, const int* in_sizes, int n_in,
                              void* d_out, int out_size) {
    const float* F  = (const float*)d_in[1];
    const float* AM = (const float*)d_in[2];
    const float* W1 = (const float*)d_in[4];
    const float* b1 = (const float*)d_in[5];
    const float* Wc = (const float*)d_in[6];
    const float* bc = (const float*)d_in[7];
    const float* Wr = (const float*)d_in[8];
    const float* br = (const float*)d_in[9];
    float* out = (float*)d_out;

    pack_kernel<<<(CIN * 64 + 255) / 256, 256>>>(Wc, bc, Wr, br);
    conv3x3_kernel<<<dim3(250, 2), 256>>>(F, W1, b1);
    head_kernel<<<500, 256>>>(out);

    // stable descending radix sort of (score-bits, index): matches lax.top_k order incl. ties
    void *kin, *kout, *vin, *vout, *tmp;
    cudaGetSymbolAddress(&kin, g_keys_in);
    cudaGetSymbolAddress(&kout, g_keys_out);
    cudaGetSymbolAddress(&vin, g_vals_in);
    cudaGetSymbolAddress(&vout, g_vals_out);
    cudaGetSymbolAddress(&tmp, g_cub_temp);
    size_t tb = 0;
    cub::DeviceRadixSort::SortPairsDescending(
        nullptr, tb, (const unsigned*)kin, (unsigned*)kout,
        (const unsigned*)vin, (unsigned*)vout, NANCH, 0, 32, (cudaStream_t)0);
    if (tb <= (size_t)CUB_TEMP_CAP) {
        cub::DeviceRadixSort::SortPairsDescending(
            tmp, tb, (const unsigned*)kin, (unsigned*)kout,
            (const unsigned*)vin, (unsigned*)vout, NANCH, 0, 32, (cudaStream_t)0);
    }

    decode_kernel<<<(PRE + 255) / 256, 256>>>(AM, out);
    nms_kernel<<<1, 1024>>>(out + PROP_OFF);
}

// round 7
// speedup vs baseline: 1.9905x; 1.9905x over previous
#include <cuda_runtime.h>
#include <cuda_bf16.h>
#include <cub/cub.cuh>
#include <math.h>

#define FHh 100
#define FWw 160
#define NPIX 16000
#define CIN 512
#define NANCH 144000
#define PRE 6000
#define POST 300
#define SCORES_OFF 0
#define REG_OFF 144000
#define PROP_OFF 720000
#define CUB_TEMP_CAP (1 << 24)
#define NCHUNK 288   // 9 taps x 32 ic-chunks of 16

// ---------------- static device scratch (no allocations allowed) ----------------
__device__ __align__(256) float g_y[NPIX * CIN];        // relu(conv1) output, NHWC
__device__ __align__(256) float g_wf[CIN * 64];          // fused 1x1 weights [ic][64]
__device__ float g_bf[64];                               // fused bias
__device__ __align__(256) unsigned g_keys_in[NANCH];
__device__ __align__(256) unsigned g_vals_in[NANCH];
__device__ __align__(256) unsigned g_keys_out[NANCH];
__device__ __align__(256) unsigned g_vals_out[NANCH];
__device__ __align__(256) unsigned char g_cub_temp[CUB_TEMP_CAP];
__device__ __align__(256) float4 g_boxes[PRE];
__device__ int g_valid[PRE];

// ---------------- cp.async helpers ----------------
__device__ __forceinline__ unsigned smem_u32(const void* p) {
    unsigned a;
    asm("{ .reg .u64 t; cvta.to.shared.u64 t, %1; cvt.u32.u64 %0, t; }" : "=r"(a) : "l"(p));
    return a;
}
#define CPA16(dst, src, sz) \
    asm volatile("cp.async.cg.shared.global [%0], [%1], 16, %2;" \
                 :: "r"(dst), "l"(src), "r"(sz) : "memory")
#define CPA_COMMIT() asm volatile("cp.async.commit_group;" ::: "memory")
#define CPA_WAIT1() asm volatile("cp.async.wait_group 1;" ::: "memory")
#define CPA_WAIT0() asm volatile("cp.async.wait_group 0;" ::: "memory")

// ---------------- pack fused 1x1 weights ----------------
__global__ void pack_kernel(const float* __restrict__ Wc, const float* __restrict__ bc,
                            const float* __restrict__ Wr, const float* __restrict__ br) {
    int i = blockIdx.x * blockDim.x + threadIdx.x;
    if (i < CIN * 64) {
        int ic = i >> 6, o = i & 63;
        float v = 0.f;
        if (o < 9)       v = Wc[ic * 9 + o];
        else if (o < 45) v = Wr[ic * 36 + (o - 9)];
        g_wf[i] = v;
    }
    if (i < 64) {
        float v = 0.f;
        if (i < 9)       v = bc[i];
        else if (i < 45) v = br[i - 9];
        g_bf[i] = v;
    }
}

// ---------------- 3x3 conv 512->512 + bias + relu ----------------
// block: 64 pixels x 128 oc, 256 threads, thread = 4px x 8oc (32 accums; R1 numerics).
// cp.async double-buffered staging of weights (16ic x 128oc) AND activations (64px x 16ic).
__global__ __launch_bounds__(256, 3)
void conv3x3_kernel(const float* __restrict__ F, const float* __restrict__ W1,
                    const float* __restrict__ b1) {
    __shared__ float4 Wbuf[2][16 * 32];   // [ic16][oc128] as float4, 8KB each
    __shared__ float  Abuf[2][64 * 16];   // [px64][ic16], 4KB each

    const int tid = threadIdx.x;
    const int pg = tid >> 4;          // 0..15
    const int ocg = tid & 15;         // 0..15
    const int pbase = blockIdx.x * 64;
    const int ocblk = blockIdx.y * 128;
    const int oc = ocblk + ocg * 8;

    // staging roles
    const int ap = tid >> 2;          // 0..63 pixel for act staging
    const int ag = tid & 3;           // ic-quad for act staging
    const int apy = (pbase + ap) / FWw;
    const int apx = (pbase + ap) % FWw;
    const int wr = tid >> 4;          // ic row for weight staging
    const int wc4 = (tid & 15) * 2;   // float4 index (2 consecutive per thread)

    const unsigned a_sdst0 = smem_u32(&Abuf[0][0]) + tid * 16;
    const unsigned a_sdst1 = smem_u32(&Abuf[1][0]) + tid * 16;
    const unsigned w_sdst0 = smem_u32(&Wbuf[0][0]) + (wr * 32 + wc4) * 16;
    const unsigned w_sdst1 = smem_u32(&Wbuf[1][0]) + (wr * 32 + wc4) * 16;

    float acc[4][8];
#pragma unroll
    for (int k = 0; k < 4; k++)
#pragma unroll
        for (int j = 0; j < 8; j++) acc[k][j] = 0.f;

    // ---- stage chunk c into buffer b ----
    auto stage = [&](int c, int b) {
        const int tap = c >> 5;
        const int icc = c & 31;
        const int dy = tap / 3 - 1, dx = tap % 3 - 1;
        // activations: one 16B vector per thread
        const int yy = apy + dy, xx = apx + dx;
        const bool v = ((unsigned)yy < (unsigned)FHh) && ((unsigned)xx < (unsigned)FWw);
        const float* asrc = F + ((size_t)(v ? (yy * FWw + xx) : 0) * CIN + icc * 16 + ag * 4);
        CPA16(b ? a_sdst1 : a_sdst0, asrc, v ? 16u : 0u);
        // weights: two 16B vectors per thread
        const float* wsrc = W1 + (size_t)tap * CIN * CIN + (size_t)(icc * 16 + wr) * CIN + ocblk + wc4 * 4;
        CPA16((b ? w_sdst1 : w_sdst0), wsrc, 16u);
        CPA16((b ? w_sdst1 : w_sdst0) + 16, wsrc + 4, 16u);
    };

    stage(0, 0);
    CPA_COMMIT();

    for (int c = 0; c < NCHUNK; c++) {
        const int buf = c & 1;
        if (c < NCHUNK - 1) {
            stage(c + 1, buf ^ 1);
            CPA_COMMIT();
            CPA_WAIT1();
        } else {
            CPA_WAIT0();
        }
        __syncthreads();

        const float* A = &Abuf[buf][0];
        const float4* W = &Wbuf[buf][0];
#pragma unroll
        for (int i = 0; i < 16; i++) {
            float av[4];
            av[0] = A[(pg * 4 + 0) * 16 + i];
            av[1] = A[(pg * 4 + 1) * 16 + i];
            av[2] = A[(pg * 4 + 2) * 16 + i];
            av[3] = A[(pg * 4 + 3) * 16 + i];
            float4 w0 = W[i * 32 + ocg * 2];
            float4 w1 = W[i * 32 + ocg * 2 + 1];
            float wv[8] = {w0.x, w0.y, w0.z, w0.w, w1.x, w1.y, w1.z, w1.w};
#pragma unroll
            for (int k = 0; k < 4; k++)
#pragma unroll
                for (int j = 0; j < 8; j++) acc[k][j] += av[k] * wv[j];
        }
        __syncthreads();
    }

    // epilogue: +bias, relu, store
    float4 bv0 = *(const float4*)(b1 + oc);
    float4 bv1 = *(const float4*)(b1 + oc + 4);
    float bb[8] = {bv0.x, bv0.y, bv0.z, bv0.w, bv1.x, bv1.y, bv1.z, bv1.w};
#pragma unroll
    for (int k = 0; k < 4; k++) {
        int p = pbase + pg * 4 + k;
        float4 o0, o1;
        o0.x = fmaxf(acc[k][0] + bb[0], 0.f);
        o0.y = fmaxf(acc[k][1] + bb[1], 0.f);
        o0.z = fmaxf(acc[k][2] + bb[2], 0.f);
        o0.w = fmaxf(acc[k][3] + bb[3], 0.f);
        o1.x = fmaxf(acc[k][4] + bb[4], 0.f);
        o1.y = fmaxf(acc[k][5] + bb[5], 0.f);
        o1.z = fmaxf(acc[k][6] + bb[6], 0.f);
        o1.w = fmaxf(acc[k][7] + bb[7], 0.f);
        *(float4*)&g_y[(size_t)p * CIN + oc]     = o0;
        *(float4*)&g_y[(size_t)p * CIN + oc + 4] = o1;
    }
}

// ---------------- fused 1x1 heads: scores (sigmoid) + reg, emit sort keys ----------------
__global__ __launch_bounds__(256)
void head_kernel(float* __restrict__ out) {
    const int tid = threadIdx.x;
    const int pxi = blockIdx.x * 32 + (tid >> 3);
    const int grp = tid & 7;

    float acc[8];
#pragma unroll
    for (int j = 0; j < 8; j++) acc[j] = g_bf[grp * 8 + j];

    const float* yrow = g_y + (size_t)pxi * CIN;
    const float4* wf4 = (const float4*)g_wf;
#pragma unroll 4
    for (int ic = 0; ic < CIN; ic++) {
        float a = __ldg(yrow + ic);
        float4 w0 = __ldg(wf4 + ic * 16 + grp * 2);
        float4 w1 = __ldg(wf4 + ic * 16 + grp * 2 + 1);
        acc[0] += a * w0.x; acc[1] += a * w0.y; acc[2] += a * w0.z; acc[3] += a * w0.w;
        acc[4] += a * w1.x; acc[5] += a * w1.y; acc[6] += a * w1.z; acc[7] += a * w1.w;
    }

#pragma unroll
    for (int j = 0; j < 8; j++) {
        int o = grp * 8 + j;
        if (o < 9) {
            float s = 1.f / (1.f + expf(-acc[j]));
            int idx = pxi * 9 + o;
            out[SCORES_OFF + idx] = s;
            g_keys_in[idx] = __float_as_uint(s);  // positive floats: uint order == float order
            g_vals_in[idx] = (unsigned)idx;
        } else if (o < 45) {
            out[REG_OFF + pxi * 36 + (o - 9)] = acc[j];
        }
    }
}

// ---------------- decode + clip + min-size for the top-6000 ----------------
__global__ void decode_kernel(const float* __restrict__ AM, const float* __restrict__ out) {
    int r = blockIdx.x * blockDim.x + threadIdx.x;
    if (r >= PRE) return;
    int idx = (int)g_vals_out[r];
    float4 an = __ldg((const float4*)AM + idx);
    float4 dl = *(const float4*)(out + REG_OFF + (size_t)idx * 4);
    float ah = an.z - an.x, aw = an.w - an.y;
    float acy = an.x + 0.5f * ah, acx = an.y + 0.5f * aw;
    float cy = acy + dl.x * ah, cx = acx + dl.y * aw;
    float h = ah * expf(dl.z), w = aw * expf(dl.w);
    float y1 = fmaxf(cy - 0.5f * h, 0.f);
    float x1 = fmaxf(cx - 0.5f * w, 0.f);
    float y2 = fminf(cy + 0.5f * h, 1600.f);
    float x2 = fminf(cx + 0.5f * w, 2560.f);
    g_boxes[r] = make_float4(y1, x1, y2, x2);
    g_valid[r] = (((y2 - y1) >= 16.f) && ((x2 - x1) >= 16.f)) ? 1 : 0;
}

// ---------------- greedy NMS (== reference argmax/suppress scan), single block ----------------
__global__ __launch_bounds__(1024)
void nms_kernel(float* __restrict__ outp) {
    __shared__ unsigned char alive[PRE];
    __shared__ int s_found;
    __shared__ int s_ptr;
    __shared__ float4 s_box;

    const int tid = threadIdx.x;
    for (int i = tid; i < PRE; i += 1024) alive[i] = (unsigned char)g_valid[i];
    if (tid == 0) s_ptr = 0;
    __syncthreads();

    for (int slot = 0; slot < POST; slot++) {
        if (tid < 32) {
            int p = s_ptr;
            int found = -1;
            while (p < PRE) {
                int i = p + tid;
                bool a = (i < PRE) && alive[i];
                unsigned m = __ballot_sync(0xffffffffu, a);
                if (m) { found = p + __ffs(m) - 1; break; }
                p += 32;
            }
            if (tid == 0) {
                s_found = found;
                if (found >= 0) {
                    alive[found] = 0;
                    s_ptr = found + 1;
                    s_box = g_boxes[found];
                } else {
                    s_ptr = PRE;
                }
            }
        }
        __syncthreads();
        int f = s_found;
        if (f < 0) {
            for (int i = slot * 4 + tid; i < POST * 4; i += 1024) outp[i] = 0.f;
            return;
        }
        float4 b = s_box;
        if (tid == 0) {
            outp[slot * 4 + 0] = b.x;
            outp[slot * 4 + 1] = b.y;
            outp[slot * 4 + 2] = b.z;
            outp[slot * 4 + 3] = b.w;
        }
        float ba = fmaxf(b.z - b.x, 0.f) * fmaxf(b.w - b.y, 0.f);
        for (int i = f + 1 + tid; i < PRE; i += 1024) {
            if (alive[i]) {
                float4 c = __ldg((const float4*)g_boxes + i);
                float yy1 = fmaxf(b.x, c.x), xx1 = fmaxf(b.y, c.y);
                float yy2 = fminf(b.z, c.z), xx2 = fminf(b.w, c.w);
                float inter = fmaxf(yy2 - yy1, 0.f) * fmaxf(xx2 - xx1, 0.f);
                float ca = fmaxf(c.z - c.x, 0.f) * fmaxf(c.w - c.y, 0.f);
                float iou = inter / (ba + ca - inter + 1e-8f);
                if (iou > 0.7f) alive[i] = 0;
            }
        }
        __syncthreads();
    }
}

// ---------------- host launcher ----------------
extern "C" void kernel_launch(void* const* d_in, const int* in_sizes, int n_in,
                              void* d_out, int out_size) {
    const float* F  = (const float*)d_in[1];
    const float* AM = (const float*)d_in[2];
    const float* W1 = (const float*)d_in[4];
    const float* b1 = (const float*)d_in[5];
    const float* Wc = (const float*)d_in[6];
    const float* bc = (const float*)d_in[7];
    const float* Wr = (const float*)d_in[8];
    const float* br = (const float*)d_in[9];
    float* out = (float*)d_out;

    pack_kernel<<<(CIN * 64 + 255) / 256, 256>>>(Wc, bc, Wr, br);
    conv3x3_kernel<<<dim3(250, 4), 256>>>(F, W1, b1);
    head_kernel<<<500, 256>>>(out);

    // stable descending radix sort of (score-bits, index): matches lax.top_k order incl. ties
    void *kin, *kout, *vin, *vout, *tmp;
    cudaGetSymbolAddress(&kin, g_keys_in);
    cudaGetSymbolAddress(&kout, g_keys_out);
    cudaGetSymbolAddress(&vin, g_vals_in);
    cudaGetSymbolAddress(&vout, g_vals_out);
    cudaGetSymbolAddress(&tmp, g_cub_temp);
    size_t tb = 0;
    cub::DeviceRadixSort::SortPairsDescending(
        nullptr, tb, (const unsigned*)kin, (unsigned*)kout,
        (const unsigned*)vin, (unsigned*)vout, NANCH, 0, 32, (cudaStream_t)0);
    if (tb <= (size_t)CUB_TEMP_CAP) {
        cub::DeviceRadixSort::SortPairsDescending(
            tmp, tb, (const unsigned*)kin, (unsigned*)kout,
            (const unsigned*)vin, (unsigned*)vout, NANCH, 0, 32, (cudaStream_t)0);
    }

    decode_kernel<<<(PRE + 255) / 256, 256>>>(AM, out);
    nms_kernel<<<1, 1024>>>(out + PROP_OFF);
}